// round 7
// baseline (speedup 1.0000x reference)
#include <cuda_runtime.h>
#include <stdint.h>

#define NUM_LABELS 100000
#define EMBED      128
#define NTOK       (16 * 4096)

#define BIN_LABELS 64
#define NBINS      ((NUM_LABELS + BIN_LABELS - 1) / BIN_LABELS)   // 1563
#define CAP        1024                                            // slots per bin (mean load 42)

// __device__ scratch (no cudaMalloc). Zero-initialized at module load;
// fused_kernel resets cursors after use so every call starts from zeros.
__device__ int g_cursor[NBINS];
__device__ int g_list[NBINS * CAP];    // packed entries: (token << 6) | local_label

// ---------------------------------------------------------------------------
// K1: bin tokens by 64-label range. entry = (token << 6) | (label % 64).
//     Overflow (pos >= CAP, impossible for this input) is handled inline by a
//     direct strided gather so no extra kernel/launch is ever needed.
// ---------------------------------------------------------------------------
__global__ __launch_bounds__(256) void bin_kernel(const int* __restrict__ X,
                                                  const float* __restrict__ W,
                                                  const float* __restrict__ bias,
                                                  float* __restrict__ out) {
    const int t = blockIdx.x * 256 + threadIdx.x;   // grid covers NTOK exactly
    int idx = X[t];
    if (idx < 0) idx = 0;
    if (idx >= NUM_LABELS) idx = NUM_LABELS - 1;    // never fault

    const int bin = idx >> 6;
    const int pos = atomicAdd(&g_cursor[bin], 1);
    if (pos < CAP) {
        g_list[bin * CAP + pos] = (t << 6) | (idx & 63);
    } else {
        // Guaranteed-correct slow path; count == 0 in practice.
        float* o = out + (size_t)t * EMBED;
        for (int e = 0; e < EMBED; e++)
            o[e] = W[(size_t)e * NUM_LABELS + idx] + bias[e];
    }
}

// ---------------------------------------------------------------------------
// K2: fused transpose + scatter + bias.
//   Block b: load W[:, b*64 .. b*64+63] into a chunk-swizzled SMEM tile,
//   then for each token in bin b write out[token][:] = tile row + bias.
//
//   SMEM layout: tile[l][ (c ^ (l&7)) * 4 + j ], row pitch 128 words (512B,
//   16B-aligned). Logical float4-chunk c lives at physical chunk c^(l&7):
//     * load  (fixed c per instr, l = lane):  STS.128 conflict-free
//     * scatter (fixed l, c = lane):          LDS.128 conflict-free
//   Global loads: 128B coalesced per warp. Global stores: STG.128, 512B
//   contiguous per token (full lines).
//   After reading its count, the block resets g_cursor[bin] = 0 for the next
//   graph replay (cursors thus always start from zero).
// ---------------------------------------------------------------------------
__global__ __launch_bounds__(256) void fused_kernel(const float* __restrict__ W,
                                                    const float* __restrict__ bias,
                                                    float* __restrict__ out) {
    __shared__ float  tile[BIN_LABELS][EMBED];      // 32 KB, swizzled chunks
    __shared__ float4 bs4[32];
    __shared__ int    entries[256];
    __shared__ int    s_count;

    const int bin = blockIdx.x;
    const int l0  = bin << 6;
    const int tid = threadIdx.x;

    if (tid < 32) bs4[tid] = reinterpret_cast<const float4*>(bias)[tid];
    if (tid == 0) {
        s_count = g_cursor[bin];
        g_cursor[bin] = 0;                          // reset for next replay
    }

    // Tile load: lane -> label (coalesced 128B/warp); each thread owns one
    // label and the 32-element e-range [32*e0, 32*e0+32) => 8 swizzled STS.128.
    {
        const int l  = tid & (BIN_LABELS - 1);      // 0..63
        const int e0 = tid >> 6;                    // 0..3
        const bool valid = (l0 + l) < NUM_LABELS;
        const int  sw = l & 7;
        #pragma unroll
        for (int cc = 0; cc < 8; cc++) {
            const int c = e0 * 8 + cc;              // logical chunk 0..31
            float r0 = 0.f, r1 = 0.f, r2 = 0.f, r3 = 0.f;
            if (valid) {
                const size_t base = (size_t)(c * 4) * NUM_LABELS + (l0 + l);
                r0 = W[base];
                r1 = W[base + (size_t)NUM_LABELS];
                r2 = W[base + (size_t)2 * NUM_LABELS];
                r3 = W[base + (size_t)3 * NUM_LABELS];
            }
            const int p = c ^ sw;                   // physical chunk
            *reinterpret_cast<float4*>(&tile[l][p * 4]) = make_float4(r0, r1, r2, r3);
        }
    }
    __syncthreads();

    int count = s_count;
    if (count > CAP) count = CAP;

    const int warp = tid >> 5;
    const int lane = tid & 31;
    const float4 bb = bs4[lane];

    for (int base = 0; base < count; base += 256) {
        const int n = min(256, count - base);
        if (tid < n) entries[tid] = g_list[bin * CAP + base + tid];
        __syncthreads();

        for (int i = warp; i < n; i += 8) {         // one warp per token
            const int ent = entries[i];
            const int tok = ent >> 6;
            const int lab = ent & 63;
            const int p   = lane ^ (lab & 7);       // logical chunk 'lane'
            float4 v = *reinterpret_cast<const float4*>(&tile[lab][p * 4]);
            v.x += bb.x; v.y += bb.y; v.z += bb.z; v.w += bb.w;
            reinterpret_cast<float4*>(out)[(size_t)tok * 32 + lane] = v;
        }
        __syncthreads();                            // entries reusable
    }
}

// ---------------------------------------------------------------------------
// Launch (2 kernels). Inputs identified by element count:
//   65536 -> X (int32), 12800000 -> W (f32 [EMBED,NUM_LABELS]), 128 -> b
// ---------------------------------------------------------------------------
extern "C" void kernel_launch(void* const* d_in, const int* in_sizes, int n_in,
                              void* d_out, int out_size) {
    const int*   X = nullptr;
    const float* W = nullptr;
    const float* b = nullptr;

    for (int i = 0; i < n_in; i++) {
        if (in_sizes[i] == NTOK)                    X = (const int*)d_in[i];
        else if (in_sizes[i] == EMBED * NUM_LABELS) W = (const float*)d_in[i];
        else if (in_sizes[i] == EMBED)              b = (const float*)d_in[i];
    }
    if (!X) X = (const int*)d_in[0];
    if (!W) W = (const float*)d_in[1];
    if (!b) b = (const float*)d_in[2];

    float* out = (float*)d_out;

    bin_kernel<<<NTOK / 256, 256>>>(X, W, b, out);
    fused_kernel<<<NBINS, 256>>>(W, b, out);
}